// round 16
// baseline (speedup 1.0000x reference)
#include <cuda_runtime.h>
#include <cuda_bf16.h>
#include <math.h>
#include <stdint.h>

#define BATCH 4096
#define CELLS 1024
#define KSTRIDE (BATCH*CELLS)   // 4194304 elements per (k) slab

// ======================= helpers (baseline PTX only) =======================
__device__ __forceinline__ uint32_t smem_to_u32(const void* smem_ptr) {
    uint32_t addr;
    asm("{ .reg .u64 tmp; cvta.to.shared.u64 tmp, %1; cvt.u32.u64 %0, tmp; }"
        : "=r"(addr) : "l"(smem_ptr));
    return addr;
}
#define LDSM_X4(r, addr) \
    asm volatile("ldmatrix.sync.aligned.m8n8.x4.shared.b16 {%0,%1,%2,%3}, [%4];" \
        : "=r"((r)[0]), "=r"((r)[1]), "=r"((r)[2]), "=r"((r)[3]) : "r"(addr))
#define CP_ASYNC_16(dst, src) \
    asm volatile("cp.async.cg.shared.global [%0], [%1], 16;" :: "r"(dst), "l"(src) : "memory")
#define CP_ASYNC_COMMIT() asm volatile("cp.async.commit_group;" ::: "memory")
#define CP_ASYNC_WAIT_1() asm volatile("cp.async.wait_group 1;" ::: "memory")
#define CP_ASYNC_WAIT_0() asm volatile("cp.async.wait_group 0;" ::: "memory")

__device__ __forceinline__ void mma_16816_bf16(float* c, const uint32_t* a,
                                               uint32_t b0, uint32_t b1) {
    asm volatile(
        "mma.sync.aligned.m16n8k16.row.col.f32.bf16.bf16.f32 "
        "{%0,%1,%2,%3}, {%4,%5,%6,%7}, {%8,%9}, {%0,%1,%2,%3};"
        : "+f"(c[0]), "+f"(c[1]), "+f"(c[2]), "+f"(c[3])
        : "r"(a[0]), "r"(a[1]), "r"(a[2]), "r"(a[3]), "r"(b0), "r"(b1));
}

// smem tile: 128 rows x 32 cols bf16 = 8KB, row = 64B = 4 chunks of 16B.
// XOR swizzle: physical chunk = c ^ ((row>>1)&3). Conflict-free for ldmatrix.
__device__ __forceinline__ uint32_t swz(uint32_t row, uint32_t c) {
    return row * 64u + ((c ^ ((row >> 1) & 3u)) * 16u);
}

// ======================= device global scratch =======================
__device__ __nv_bfloat16 g_Bhi_empty[CELLS*CELLS];
__device__ __nv_bfloat16 g_Blo_empty[CELLS*CELLS];
__device__ __nv_bfloat16 g_Bhi_each [CELLS*CELLS];
__device__ __nv_bfloat16 g_Blo_each [CELLS*CELLS];
__device__ __nv_bfloat16 g_Bhi_not  [CELLS*CELLS];
__device__ __nv_bfloat16 g_Blo_not  [CELLS*CELLS];
__device__ __nv_bfloat16 g_Bhi_not2 [CELLS*CELLS];
__device__ __nv_bfloat16 g_Blo_not2 [CELLS*CELLS];

__device__ __nv_bfloat16 g_emptyA[KSTRIDE];       // exact 0/1 masks in bf16
__device__ __nv_bfloat16 g_eachA [4*KSTRIDE];
// ping-pong X buffers (split of X = N*s)
__device__ __nv_bfloat16 g_Xhi0  [4*KSTRIDE];
__device__ __nv_bfloat16 g_Xlo0  [4*KSTRIDE];
__device__ __nv_bfloat16 g_Xhi1  [4*KSTRIDE];
__device__ __nv_bfloat16 g_Xlo1  [4*KSTRIDE];

__device__ float g_E   [KSTRIDE];
__device__ float g_P   [4*KSTRIDE];
__device__ float g_N   [4*KSTRIDE];
__device__ float g_Asel[KSTRIDE];    // Aea masked to own class, single slab
__device__ float g_a   [KSTRIDE];
__device__ float g_s   [KSTRIDE];
__device__ unsigned char g_cls[KSTRIDE];
__device__ float g_x1[BATCH*100];
__device__ float g_x2[BATCH*100];

// ======= build transposed conv matrices, split to bf16 hi/lo =======
__global__ void build_B_k(const float* __restrict__ w_each,
                          const float* __restrict__ w_not,
                          const float* __restrict__ w_not2,
                          const float* __restrict__ w_empty) {
    int idx = blockIdx.x * blockDim.x + threadIdx.x;
    if (idx >= CELLS*CELLS) return;
    int n = idx >> 10;      // output cell (row of B)
    int k = idx & 1023;     // input cell  (col of B)
    int ny = n >> 5, nx = n & 31;
    int kv = k >> 5, kh = k & 31;
    int dy = kv - ny + 16, dx = kh - nx + 16;
    float we = 0.f, wa = 0.f, wn = 0.f, w2 = 0.f;
    if ((unsigned)dy < 33u && (unsigned)dx < 33u) {
        int wi = dy * 33 + dx;
        we = w_empty[wi]; wa = w_each[wi]; wn = w_not[wi]; w2 = w_not2[wi];
    }
    __nv_bfloat16 h;
    h = __float2bfloat16(we); g_Bhi_empty[idx] = h; g_Blo_empty[idx] = __float2bfloat16(we - __bfloat162float(h));
    h = __float2bfloat16(wa); g_Bhi_each [idx] = h; g_Blo_each [idx] = __float2bfloat16(wa - __bfloat162float(h));
    h = __float2bfloat16(wn); g_Bhi_not  [idx] = h; g_Blo_not  [idx] = __float2bfloat16(wn - __bfloat162float(h));
    h = __float2bfloat16(w2); g_Bhi_not2 [idx] = h; g_Blo_not2 [idx] = __float2bfloat16(w2 - __bfloat162float(h));
}

// ======= masks (bf16, exact 0/1) =======
__global__ void build_masks_k(const int* __restrict__ dots) {
    int idx = blockIdx.x * blockDim.x + threadIdx.x;
    if (idx >= KSTRIDE) return;
    int b = idx >> 10;
    int i = idx & 1023;
    int c = dots[i * BATCH + b];   // dots[(v*32+h)*B + b]
    g_cls[idx] = (unsigned char)c;
    g_emptyA[idx] = __float2bfloat16((c == 0) ? 1.f : 0.f);
#pragma unroll
    for (int k = 0; k < 4; k++)
        g_eachA[k*KSTRIDE + idx] = __float2bfloat16((c == k + 1) ? 1.f : 0.f);
}

// ======= bf16 mma.sync GEMM with interleaved K-segments =======
// CTA tile 128x128, Kt=32, 32 k-tiles; per tile load {A0[,A1],Bhi,Blo} once:
//   phase A (exact A): acc += A@Bhi + A@Blo                (2 passes)
//   diffusion:         acc += Ahi@Bhi + Ahi@Blo + Alo@Bhi  (3 passes)
// 8 warps (2M x 4N), warp tile 64x32, 3-stage cp.async, swizzled 8KB tiles.
// sel==1: phase A combined launch. bx<8: Asel(masked); 8<=bx<16: P(full);
//         16<=bx<24: E(full, rows<4096 only).
// sel==3: diffusion, fused update epilogue. par = X ping-pong parity,
//         fin = final depth (write g_s instead of a/X).
#define TILEB 8192
#define STAGEB (4*TILEB)         // A0,A1,B0,B1 slots = 32KB
extern __shared__ unsigned char dyn_smem[];

__global__ __launch_bounds__(256, 2)
void mma_gemm_k(int sel, int par, int fin) {
    const __nv_bfloat16 *A0, *A1 = nullptr;
    const __nv_bfloat16 *B0, *B1;
    float* C = nullptr;
    __nv_bfloat16 *Xho = nullptr, *Xlo = nullptr;   // diffusion X output buffers
    int npass;
    int mode;                    // 0=full store, 1=masked store (Asel), 2=fused update
    int bx = blockIdx.x;
    size_t nBase;
    if (sel == 1) {
        npass = 2; mode = 0;
        if (bx < 8) {
            A0 = g_eachA; B0 = g_Bhi_each; B1 = g_Blo_each; C = g_Asel; mode = 1;
            nBase = (size_t)bx * 128;
        } else if (bx < 16) {
            A0 = g_eachA; B0 = g_Bhi_not; B1 = g_Blo_not; C = g_P;
            nBase = (size_t)(bx - 8) * 128;
        } else {
            if (blockIdx.y >= 32) return;       // E has only 4096 rows
            A0 = g_emptyA; B0 = g_Bhi_empty; B1 = g_Blo_empty; C = g_E;
            nBase = (size_t)(bx - 16) * 128;
        }
    } else {
        npass = 3; mode = 2;
        if (par == 0) { A0 = g_Xhi0; A1 = g_Xlo0; Xho = g_Xhi1; Xlo = g_Xlo1; }
        else          { A0 = g_Xhi1; A1 = g_Xlo1; Xho = g_Xhi0; Xlo = g_Xlo0; }
        B0 = g_Bhi_not2; B1 = g_Blo_not2;
        nBase = (size_t)bx * 128;
    }

    const uint32_t sBase = smem_to_u32(dyn_smem);

    const int tid  = threadIdx.x;
    const int lane = tid & 31;
    const int wid  = tid >> 5;
    const int wm   = wid & 1;          // 2 warps along M
    const int wn   = wid >> 1;         // 4 warps along N (32 cols each)
    const size_t mBase = (size_t)blockIdx.y * 128;

    const int NT = 32;                 // 32 k-tiles cover K=1024

    const int rr = tid >> 2;
    const int cc = tid & 3;

    float acc[4][4][4];
#pragma unroll
    for (int i = 0; i < 4; i++)
#pragma unroll
        for (int j = 0; j < 4; j++)
#pragma unroll
            for (int q = 0; q < 4; q++) acc[i][j][q] = 0.f;

    auto load_tile = [&](uint32_t dstBase, const __nv_bfloat16* src, size_t rowBase, int kk) {
#pragma unroll
        for (int i = 0; i < 2; i++) {
            uint32_t row = (uint32_t)(rr + i * 64);
            CP_ASYNC_16(dstBase + swz(row, (uint32_t)cc),
                        src + (rowBase + row) * 1024 + kk + cc * 8);
        }
    };
    auto issue_tile = [&](int t, int stage) {
        int kk = t * 32;
        uint32_t base = sBase + (uint32_t)stage * STAGEB;
        load_tile(base,             A0, mBase, kk);
        if (npass == 3) load_tile(base + TILEB, A1, mBase, kk);
        load_tile(base + 2*TILEB,   B0, nBase, kk);
        load_tile(base + 3*TILEB,   B1, nBase, kk);
        CP_ASYNC_COMMIT();
    };

    issue_tile(0, 0);
    issue_tile(1, 1);

    int stage = 0;
    for (int t = 0; t < NT; ++t) {
        if (t < NT - 1) CP_ASYNC_WAIT_1();
        else            CP_ASYNC_WAIT_0();
        __syncthreads();

        uint32_t base = sBase + (uint32_t)stage * STAGEB;
#pragma unroll
        for (int ks = 0; ks < 2; ks++) {
            const uint32_t cA = (uint32_t)(ks * 2);
            uint32_t bfr0[2][4], bfr1[2][4], afr[4][4];
#pragma unroll
            for (int nb = 0; nb < 2; nb++) {
                uint32_t row = (uint32_t)(wn * 32 + nb * 16 + (lane & 15));
                uint32_t c   = cA + (uint32_t)(lane >> 4);
                LDSM_X4(bfr0[nb], base + 2*TILEB + swz(row, c));
                LDSM_X4(bfr1[nb], base + 3*TILEB + swz(row, c));
            }
#pragma unroll
            for (int mi = 0; mi < 4; mi++) {
                uint32_t row = (uint32_t)(wm * 64 + mi * 16 + (lane & 15));
                uint32_t c   = cA + (uint32_t)(lane >> 4);
                LDSM_X4(afr[mi], base + swz(row, c));
            }
            // pass 1: A0 @ Bhi
#pragma unroll
            for (int mi = 0; mi < 4; mi++)
#pragma unroll
                for (int j = 0; j < 4; j++) {
                    int nb = j >> 1, h = j & 1;
                    mma_16816_bf16(acc[mi][j], afr[mi], bfr0[nb][h], bfr0[nb][h + 2]);
                }
            // pass 2: A0 @ Blo
#pragma unroll
            for (int mi = 0; mi < 4; mi++)
#pragma unroll
                for (int j = 0; j < 4; j++) {
                    int nb = j >> 1, h = j & 1;
                    mma_16816_bf16(acc[mi][j], afr[mi], bfr1[nb][h], bfr1[nb][h + 2]);
                }
            if (npass == 3) {
                // pass 3: A1 (lo) @ Bhi
#pragma unroll
                for (int mi = 0; mi < 4; mi++) {
                    uint32_t row = (uint32_t)(wm * 64 + mi * 16 + (lane & 15));
                    uint32_t c   = cA + (uint32_t)(lane >> 4);
                    LDSM_X4(afr[mi], base + TILEB + swz(row, c));
                }
#pragma unroll
                for (int mi = 0; mi < 4; mi++)
#pragma unroll
                    for (int j = 0; j < 4; j++) {
                        int nb = j >> 1, h = j & 1;
                        mma_16816_bf16(acc[mi][j], afr[mi], bfr0[nb][h], bfr0[nb][h + 2]);
                    }
            }
        }
        if (t + 2 < NT) {
            int s2 = stage + 2; if (s2 >= 3) s2 -= 3;
            issue_tile(t + 2, s2);
        }
        if (++stage == 3) stage = 0;
    }

    // ---- epilogue ----
    const int g  = lane >> 2;
    const int t2 = (lane & 3) * 2;
    if (mode == 0) {
#pragma unroll
        for (int mi = 0; mi < 4; mi++)
#pragma unroll
            for (int j = 0; j < 4; j++) {
                size_t r = mBase + (size_t)(wm * 64 + mi * 16 + g);
                size_t c = nBase + (size_t)(wn * 32 + j * 8 + t2);
                *(float2*)&C[r * 1024 + c]       = make_float2(acc[mi][j][0], acc[mi][j][1]);
                *(float2*)&C[(r + 8) * 1024 + c] = make_float2(acc[mi][j][2], acc[mi][j][3]);
            }
    } else if (mode == 1) {
#pragma unroll
        for (int mi = 0; mi < 4; mi++)
#pragma unroll
            for (int j = 0; j < 4; j++) {
                size_t r = mBase + (size_t)(wm * 64 + mi * 16 + g);
                size_t c = nBase + (size_t)(wn * 32 + j * 8 + t2);
                int k1 = (int)(r >> 12) + 1;
                {
                    size_t e = (r & 4095) * 1024 + c;
                    if (g_cls[e]     == k1) C[e]     = acc[mi][j][0];
                    if (g_cls[e + 1] == k1) C[e + 1] = acc[mi][j][1];
                }
                {
                    size_t e = ((r + 8) & 4095) * 1024 + c;
                    if (g_cls[e]     == k1) C[e]     = acc[mi][j][2];
                    if (g_cls[e + 1] == k1) C[e + 1] = acc[mi][j][3];
                }
            }
    } else {
        // fused diffusion update: a += E + D; s = sigmoid(a); emit next X (all slabs)
        auto upd = [&](size_t e, int k1, float dval) {
            if (g_cls[e] == (unsigned char)k1) {
                float a = g_a[e] + g_E[e] + dval;
                float s = 1.f / (1.f + expf(-a));
                if (!fin) {
                    g_a[e] = a;
#pragma unroll
                    for (int k = 0; k < 4; k++) {
                        float x = g_N[(size_t)k*KSTRIDE + e] * s;
                        __nv_bfloat16 h = __float2bfloat16(x);
                        Xho[(size_t)k*KSTRIDE + e] = h;
                        Xlo[(size_t)k*KSTRIDE + e] = __float2bfloat16(x - __bfloat162float(h));
                    }
                } else {
                    g_s[e] = s;
                }
            }
        };
#pragma unroll
        for (int mi = 0; mi < 4; mi++)
#pragma unroll
            for (int j = 0; j < 4; j++) {
                size_t r = mBase + (size_t)(wm * 64 + mi * 16 + g);
                size_t c = nBase + (size_t)(wn * 32 + j * 8 + t2);
                int k1 = (int)(r >> 12) + 1;
                {
                    size_t e = (r & 4095) * 1024 + c;
                    upd(e,     k1, acc[mi][j][0]);
                    upd(e + 1, k1, acc[mi][j][1]);
                }
                {
                    size_t e = ((r + 8) & 4095) * 1024 + c;
                    upd(e,     k1, acc[mi][j][2]);
                    upd(e + 1, k1, acc[mi][j][3]);
                }
            }
    }
}

// ======= init (fused): N_k = T - P_k; a,s; X_k = N_k*s into BOTH buffers =======
__global__ void init_k() {
    int idx = blockIdx.x * blockDim.x + threadIdx.x;
    if (idx >= KSTRIDE) return;
    float P0 = g_P[0*KSTRIDE + idx];
    float P1 = g_P[1*KSTRIDE + idx];
    float P2 = g_P[2*KSTRIDE + idx];
    float P3 = g_P[3*KSTRIDE + idx];
    float T = P0 + P1 + P2 + P3;
    float N0 = T - P0, N1 = T - P1, N2 = T - P2, N3 = T - P3;
    g_N[0*KSTRIDE + idx] = N0;
    g_N[1*KSTRIDE + idx] = N1;
    g_N[2*KSTRIDE + idx] = N2;
    g_N[3*KSTRIDE + idx] = N3;
    int c = g_cls[idx];
    float a = 0.f, s = 0.5f;
    if (c != 0) {
        int k = c - 1;
        float Nk = (k == 0) ? N0 : (k == 1) ? N1 : (k == 2) ? N2 : N3;
        a = g_Asel[idx] + g_E[idx] - Nk;
        s = 1.f / (1.f + expf(-a));
    }
    g_a[idx] = a;
    g_s[idx] = s;
    float Nv[4] = {N0, N1, N2, N3};
#pragma unroll
    for (int k = 0; k < 4; k++) {
        float x = Nv[k] * s;
        __nv_bfloat16 h = __float2bfloat16(x);
        __nv_bfloat16 l = __float2bfloat16(x - __bfloat162float(h));
        g_Xhi0[k*KSTRIDE + idx] = h;
        g_Xlo0[k*KSTRIDE + idx] = l;
        g_Xhi1[k*KSTRIDE + idx] = h;   // empty cells stay valid in both buffers
        g_Xlo1[k*KSTRIDE + idx] = l;
    }
}

// ======= MLP head =======
__global__ __launch_bounds__(256)
void mlp1_k(const float* __restrict__ W1) {
    __shared__ float sS[64][65];
    __shared__ float sW[100][65];
    int tid = threadIdx.x;
    int rowBase = blockIdx.x * 64;
    float acc[25];
#pragma unroll
    for (int i = 0; i < 25; i++) acc[i] = 0.f;
    int r = tid >> 2, cs = (tid & 3) * 25;
    for (int k0 = 0; k0 < 1024; k0 += 64) {
#pragma unroll
        for (int i = 0; i < 16; i++) {
            int e = tid + i * 256; int rr = e >> 6, c = e & 63;
            sS[rr][c] = g_s[(size_t)(rowBase + rr) * 1024 + k0 + c];
        }
#pragma unroll
        for (int i = 0; i < 25; i++) {
            int e = tid + i * 256; int j = e >> 6, c = e & 63;
            sW[j][c] = W1[(size_t)j * 1024 + k0 + c];
        }
        __syncthreads();
#pragma unroll 8
        for (int k = 0; k < 64; k++) {
            float sv = sS[r][k];
#pragma unroll
            for (int j = 0; j < 25; j++) acc[j] += sv * sW[cs + j][k];
        }
        __syncthreads();
    }
#pragma unroll
    for (int j = 0; j < 25; j++) {
        float v = acc[j];
        g_x1[(size_t)(rowBase + r) * 100 + cs + j] = (v > 0.f) ? v : 0.2f * v;
    }
}

__global__ void mlp2_k(const float* __restrict__ W2) {
    int gw = (blockIdx.x * blockDim.x + threadIdx.x) >> 5;
    int lane = threadIdx.x & 31;
    if (gw >= BATCH * 100) return;
    int b = gw / 100, j = gw % 100;
    const float* xrow = g_x1 + (size_t)b * 100;
    const float* wrow = W2 + (size_t)j * 100;
    float acc = 0.f;
    for (int t = lane; t < 100; t += 32) acc += xrow[t] * wrow[t];
#pragma unroll
    for (int o = 16; o; o >>= 1) acc += __shfl_xor_sync(0xffffffffu, acc, o);
    if (lane == 0) g_x2[b * 100 + j] = (acc > 0.f) ? acc : 0.2f * acc;
}

__global__ void mlp3_k(const float* __restrict__ W3, float* __restrict__ out) {
    int gw = (blockIdx.x * blockDim.x + threadIdx.x) >> 5;
    int lane = threadIdx.x & 31;
    if (gw >= BATCH) return;
    const float* xrow = g_x2 + (size_t)gw * 100;
    float acc = 0.f;
    for (int t = lane; t < 100; t += 32) acc += xrow[t] * W3[t];
#pragma unroll
    for (int o = 16; o; o >>= 1) acc += __shfl_xor_sync(0xffffffffu, acc, o);
    if (lane == 0) out[gw] = acc;
}

// ======= launch =======
extern "C" void kernel_launch(void* const* d_in, const int* in_sizes, int n_in,
                              void* d_out, int out_size) {
    (void)in_sizes; (void)n_in; (void)out_size;
    const int*   dots    = (const int*)d_in[0];
    const float* w_each  = (const float*)d_in[1];
    const float* w_not   = (const float*)d_in[2];
    const float* w_not2  = (const float*)d_in[3];
    const float* w_empty = (const float*)d_in[4];
    const float* W1      = (const float*)d_in[5];
    const float* W2      = (const float*)d_in[6];
    const float* W3      = (const float*)d_in[7];
    float* out = (float*)d_out;

    const int SMEM = 3 * STAGEB;   // 98304
    cudaFuncSetAttribute(mma_gemm_k, cudaFuncAttributeMaxDynamicSharedMemorySize, SMEM);

    build_B_k<<<(CELLS*CELLS + 255)/256, 256>>>(w_each, w_not, w_not2, w_empty);
    build_masks_k<<<(KSTRIDE + 255)/256, 256>>>(dots);

    // phase A: Asel(masked) + P + E in one launch
    mma_gemm_k<<<dim3(24, 128), 256, SMEM>>>(1, 0, 0);

    init_k<<<(KSTRIDE + 255)/256, 256>>>();

    // 4 diffusion depths, update fused into GEMM epilogue, X ping-pong
    for (int d = 0; d < 4; d++)
        mma_gemm_k<<<dim3(8, 128), 256, SMEM>>>(3, d & 1, d == 3 ? 1 : 0);

    mlp1_k<<<BATCH/64, 256>>>(W1);
    {
        long nw = (long)BATCH * 100 * 32;
        mlp2_k<<<(unsigned)((nw + 255)/256), 256>>>(W2);
        long nw3 = (long)BATCH * 32;
        mlp3_k<<<(unsigned)((nw3 + 255)/256), 256>>>(W3, out);
    }
}

// round 17
// speedup vs baseline: 1.8240x; 1.8240x over previous
#include <cuda_runtime.h>
#include <cuda_bf16.h>
#include <math.h>
#include <stdint.h>

#define BATCH 4096
#define CELLS 1024
#define KSTRIDE (BATCH*CELLS)   // 4194304 elements per (k) slab

// ======================= helpers (baseline PTX only) =======================
__device__ __forceinline__ uint32_t smem_to_u32(const void* smem_ptr) {
    uint32_t addr;
    asm("{ .reg .u64 tmp; cvta.to.shared.u64 tmp, %1; cvt.u32.u64 %0, tmp; }"
        : "=r"(addr) : "l"(smem_ptr));
    return addr;
}
#define LDSM_X4(r, addr) \
    asm volatile("ldmatrix.sync.aligned.m8n8.x4.shared.b16 {%0,%1,%2,%3}, [%4];" \
        : "=r"((r)[0]), "=r"((r)[1]), "=r"((r)[2]), "=r"((r)[3]) : "r"(addr))
#define CP_ASYNC_16(dst, src) \
    asm volatile("cp.async.cg.shared.global [%0], [%1], 16;" :: "r"(dst), "l"(src) : "memory")
#define CP_ASYNC_COMMIT() asm volatile("cp.async.commit_group;" ::: "memory")
#define CP_ASYNC_WAIT_1() asm volatile("cp.async.wait_group 1;" ::: "memory")
#define CP_ASYNC_WAIT_0() asm volatile("cp.async.wait_group 0;" ::: "memory")

__device__ __forceinline__ void mma_16816_bf16(float* c, const uint32_t* a,
                                               uint32_t b0, uint32_t b1) {
    asm volatile(
        "mma.sync.aligned.m16n8k16.row.col.f32.bf16.bf16.f32 "
        "{%0,%1,%2,%3}, {%4,%5,%6,%7}, {%8,%9}, {%0,%1,%2,%3};"
        : "+f"(c[0]), "+f"(c[1]), "+f"(c[2]), "+f"(c[3])
        : "r"(a[0]), "r"(a[1]), "r"(a[2]), "r"(a[3]), "r"(b0), "r"(b1));
}

// smem tile: 128 rows x 32 cols bf16 = 8KB, row = 64B = 4 chunks of 16B.
// XOR swizzle: physical chunk = c ^ ((row>>1)&3). Conflict-free for ldmatrix.
__device__ __forceinline__ uint32_t swz(uint32_t row, uint32_t c) {
    return row * 64u + ((c ^ ((row >> 1) & 3u)) * 16u);
}

// ======================= device global scratch =======================
__device__ __nv_bfloat16 g_Bhi_empty[CELLS*CELLS];
__device__ __nv_bfloat16 g_Blo_empty[CELLS*CELLS];
__device__ __nv_bfloat16 g_Bhi_each [CELLS*CELLS];
__device__ __nv_bfloat16 g_Blo_each [CELLS*CELLS];
__device__ __nv_bfloat16 g_Bhi_not  [CELLS*CELLS];
__device__ __nv_bfloat16 g_Blo_not  [CELLS*CELLS];
__device__ __nv_bfloat16 g_Bhi_not2 [CELLS*CELLS];
__device__ __nv_bfloat16 g_Blo_not2 [CELLS*CELLS];

__device__ __nv_bfloat16 g_emptyA[KSTRIDE];       // exact 0/1 masks in bf16
__device__ __nv_bfloat16 g_eachA [4*KSTRIDE];
__device__ __nv_bfloat16 g_Xhi   [4*KSTRIDE];     // split of X = N*s
__device__ __nv_bfloat16 g_Xlo   [4*KSTRIDE];

__device__ float g_E   [KSTRIDE];
__device__ float g_P   [4*KSTRIDE];
__device__ float g_N   [4*KSTRIDE];
__device__ float g_Asel[KSTRIDE];    // Aea masked to own class, single slab
__device__ float g_Dsel[KSTRIDE];    // D masked to own class, single slab
__device__ float g_a   [KSTRIDE];
__device__ float g_s   [KSTRIDE];
__device__ unsigned char g_cls[KSTRIDE];
__device__ float g_x1[BATCH*100];
__device__ float g_x2[BATCH*100];

// ======= build transposed conv matrices, split to bf16 hi/lo =======
__global__ void build_B_k(const float* __restrict__ w_each,
                          const float* __restrict__ w_not,
                          const float* __restrict__ w_not2,
                          const float* __restrict__ w_empty) {
    int idx = blockIdx.x * blockDim.x + threadIdx.x;
    if (idx >= CELLS*CELLS) return;
    int n = idx >> 10;      // output cell (row of B)
    int k = idx & 1023;     // input cell  (col of B)
    int ny = n >> 5, nx = n & 31;
    int kv = k >> 5, kh = k & 31;
    int dy = kv - ny + 16, dx = kh - nx + 16;
    float we = 0.f, wa = 0.f, wn = 0.f, w2 = 0.f;
    if ((unsigned)dy < 33u && (unsigned)dx < 33u) {
        int wi = dy * 33 + dx;
        we = w_empty[wi]; wa = w_each[wi]; wn = w_not[wi]; w2 = w_not2[wi];
    }
    __nv_bfloat16 h;
    h = __float2bfloat16(we); g_Bhi_empty[idx] = h; g_Blo_empty[idx] = __float2bfloat16(we - __bfloat162float(h));
    h = __float2bfloat16(wa); g_Bhi_each [idx] = h; g_Blo_each [idx] = __float2bfloat16(wa - __bfloat162float(h));
    h = __float2bfloat16(wn); g_Bhi_not  [idx] = h; g_Blo_not  [idx] = __float2bfloat16(wn - __bfloat162float(h));
    h = __float2bfloat16(w2); g_Bhi_not2 [idx] = h; g_Blo_not2 [idx] = __float2bfloat16(w2 - __bfloat162float(h));
}

// ======= masks (bf16, exact 0/1) =======
__global__ void build_masks_k(const int* __restrict__ dots) {
    int idx = blockIdx.x * blockDim.x + threadIdx.x;
    if (idx >= KSTRIDE) return;
    int b = idx >> 10;
    int i = idx & 1023;
    int c = dots[i * BATCH + b];   // dots[(v*32+h)*B + b]
    g_cls[idx] = (unsigned char)c;
    g_emptyA[idx] = __float2bfloat16((c == 0) ? 1.f : 0.f);
#pragma unroll
    for (int k = 0; k < 4; k++)
        g_eachA[k*KSTRIDE + idx] = __float2bfloat16((c == k + 1) ? 1.f : 0.f);
}

// ======= bf16 mma.sync GEMM with interleaved K-segments =======
// CTA tile 128x128, Kt=32, 32 k-tiles; per tile load {A0[,A1],Bhi,Blo} once:
//   phase A (exact A): acc += A@Bhi + A@Blo                (2 passes)
//   diffusion:         acc += Ahi@Bhi + Ahi@Blo + Alo@Bhi  (3 passes)
// 8 warps (2M x 4N), warp tile 64x32, 3-stage cp.async, swizzled 8KB tiles.
// sel==1: phase A combined. bx<8: Asel(masked); 8<=bx<16: P(full);
//         16<=bx<24: E(full, rows<4096 only).
// sel==3: diffusion -> g_Dsel (masked).
#define TILEB 8192
#define STAGEB (4*TILEB)         // A0,A1,B0,B1 slots = 32KB
extern __shared__ unsigned char dyn_smem[];

__global__ __launch_bounds__(256, 2)
void mma_gemm_k(int sel) {
    const __nv_bfloat16 *A0, *A1 = nullptr;
    const __nv_bfloat16 *B0, *B1;
    float* C;
    int npass;
    int masked = 0;
    int bx = blockIdx.x;
    size_t nBase;
    if (sel == 1) {
        npass = 2;
        if (bx < 8) {
            A0 = g_eachA; B0 = g_Bhi_each; B1 = g_Blo_each; C = g_Asel; masked = 1;
            nBase = (size_t)bx * 128;
        } else if (bx < 16) {
            A0 = g_eachA; B0 = g_Bhi_not; B1 = g_Blo_not; C = g_P;
            nBase = (size_t)(bx - 8) * 128;
        } else {
            if (blockIdx.y >= 32) return;       // E has only 4096 rows
            A0 = g_emptyA; B0 = g_Bhi_empty; B1 = g_Blo_empty; C = g_E;
            nBase = (size_t)(bx - 16) * 128;
        }
    } else {
        A0 = g_Xhi; A1 = g_Xlo;
        B0 = g_Bhi_not2; B1 = g_Blo_not2; C = g_Dsel; masked = 1; npass = 3;
        nBase = (size_t)bx * 128;
    }

    const uint32_t sBase = smem_to_u32(dyn_smem);

    const int tid  = threadIdx.x;
    const int lane = tid & 31;
    const int wid  = tid >> 5;
    const int wm   = wid & 1;          // 2 warps along M
    const int wn   = wid >> 1;         // 4 warps along N (32 cols each)
    const size_t mBase = (size_t)blockIdx.y * 128;

    const int NT = 32;                 // 32 k-tiles cover K=1024

    const int rr = tid >> 2;
    const int cc = tid & 3;

    float acc[4][4][4];
#pragma unroll
    for (int i = 0; i < 4; i++)
#pragma unroll
        for (int j = 0; j < 4; j++)
#pragma unroll
            for (int q = 0; q < 4; q++) acc[i][j][q] = 0.f;

    auto load_tile = [&](uint32_t dstBase, const __nv_bfloat16* src, size_t rowBase, int kk) {
#pragma unroll
        for (int i = 0; i < 2; i++) {
            uint32_t row = (uint32_t)(rr + i * 64);
            CP_ASYNC_16(dstBase + swz(row, (uint32_t)cc),
                        src + (rowBase + row) * 1024 + kk + cc * 8);
        }
    };
    auto issue_tile = [&](int t, int stage) {
        int kk = t * 32;
        uint32_t base = sBase + (uint32_t)stage * STAGEB;
        load_tile(base,             A0, mBase, kk);
        if (npass == 3) load_tile(base + TILEB, A1, mBase, kk);
        load_tile(base + 2*TILEB,   B0, nBase, kk);
        load_tile(base + 3*TILEB,   B1, nBase, kk);
        CP_ASYNC_COMMIT();
    };

    issue_tile(0, 0);
    issue_tile(1, 1);

    int stage = 0;
    for (int t = 0; t < NT; ++t) {
        if (t < NT - 1) CP_ASYNC_WAIT_1();
        else            CP_ASYNC_WAIT_0();
        __syncthreads();

        uint32_t base = sBase + (uint32_t)stage * STAGEB;
#pragma unroll
        for (int ks = 0; ks < 2; ks++) {
            const uint32_t cA = (uint32_t)(ks * 2);
            uint32_t bfr0[2][4], bfr1[2][4], afr[4][4];
#pragma unroll
            for (int nb = 0; nb < 2; nb++) {
                uint32_t row = (uint32_t)(wn * 32 + nb * 16 + (lane & 15));
                uint32_t c   = cA + (uint32_t)(lane >> 4);
                LDSM_X4(bfr0[nb], base + 2*TILEB + swz(row, c));
                LDSM_X4(bfr1[nb], base + 3*TILEB + swz(row, c));
            }
#pragma unroll
            for (int mi = 0; mi < 4; mi++) {
                uint32_t row = (uint32_t)(wm * 64 + mi * 16 + (lane & 15));
                uint32_t c   = cA + (uint32_t)(lane >> 4);
                LDSM_X4(afr[mi], base + swz(row, c));
            }
            // pass 1: A0 @ Bhi
#pragma unroll
            for (int mi = 0; mi < 4; mi++)
#pragma unroll
                for (int j = 0; j < 4; j++) {
                    int nb = j >> 1, h = j & 1;
                    mma_16816_bf16(acc[mi][j], afr[mi], bfr0[nb][h], bfr0[nb][h + 2]);
                }
            // pass 2: A0 @ Blo
#pragma unroll
            for (int mi = 0; mi < 4; mi++)
#pragma unroll
                for (int j = 0; j < 4; j++) {
                    int nb = j >> 1, h = j & 1;
                    mma_16816_bf16(acc[mi][j], afr[mi], bfr1[nb][h], bfr1[nb][h + 2]);
                }
            if (npass == 3) {
                // pass 3: A1 (lo) @ Bhi
#pragma unroll
                for (int mi = 0; mi < 4; mi++) {
                    uint32_t row = (uint32_t)(wm * 64 + mi * 16 + (lane & 15));
                    uint32_t c   = cA + (uint32_t)(lane >> 4);
                    LDSM_X4(afr[mi], base + TILEB + swz(row, c));
                }
#pragma unroll
                for (int mi = 0; mi < 4; mi++)
#pragma unroll
                    for (int j = 0; j < 4; j++) {
                        int nb = j >> 1, h = j & 1;
                        mma_16816_bf16(acc[mi][j], afr[mi], bfr0[nb][h], bfr0[nb][h + 2]);
                    }
            }
        }
        if (t + 2 < NT) {
            int s2 = stage + 2; if (s2 >= 3) s2 -= 3;
            issue_tile(t + 2, s2);
        }
        if (++stage == 3) stage = 0;
    }

    // ---- epilogue ----
    const int g  = lane >> 2;
    const int t2 = (lane & 3) * 2;
    if (!masked) {
#pragma unroll
        for (int mi = 0; mi < 4; mi++)
#pragma unroll
            for (int j = 0; j < 4; j++) {
                size_t r = mBase + (size_t)(wm * 64 + mi * 16 + g);
                size_t c = nBase + (size_t)(wn * 32 + j * 8 + t2);
                *(float2*)&C[r * 1024 + c]       = make_float2(acc[mi][j][0], acc[mi][j][1]);
                *(float2*)&C[(r + 8) * 1024 + c] = make_float2(acc[mi][j][2], acc[mi][j][3]);
            }
    } else {
#pragma unroll
        for (int mi = 0; mi < 4; mi++)
#pragma unroll
            for (int j = 0; j < 4; j++) {
                size_t r = mBase + (size_t)(wm * 64 + mi * 16 + g);
                size_t c = nBase + (size_t)(wn * 32 + j * 8 + t2);
                int k1 = (int)(r >> 12) + 1;          // slab -> class id
                {
                    size_t e = (r & 4095) * 1024 + c;
                    if (g_cls[e]     == k1) C[e]     = acc[mi][j][0];
                    if (g_cls[e + 1] == k1) C[e + 1] = acc[mi][j][1];
                }
                {
                    size_t e = ((r + 8) & 4095) * 1024 + c;
                    if (g_cls[e]     == k1) C[e]     = acc[mi][j][2];
                    if (g_cls[e + 1] == k1) C[e + 1] = acc[mi][j][3];
                }
            }
    }
}

// ======= init (fused, 4-wide): N_k = T - P_k; a,s; X_k = N_k*s split =======
__global__ void init_k() {
    int v = blockIdx.x * blockDim.x + threadIdx.x;   // vector index (4 cells)
    if (v >= KSTRIDE/4) return;
    int idx = v * 4;
    float4 P0 = *(const float4*)&g_P[0*KSTRIDE + idx];
    float4 P1 = *(const float4*)&g_P[1*KSTRIDE + idx];
    float4 P2 = *(const float4*)&g_P[2*KSTRIDE + idx];
    float4 P3 = *(const float4*)&g_P[3*KSTRIDE + idx];
    float4 Ev = *(const float4*)&g_E[idx];
    float4 As = *(const float4*)&g_Asel[idx];
    uchar4 cv = *(const uchar4*)&g_cls[idx];

    float P[4][4] = {{P0.x,P0.y,P0.z,P0.w},{P1.x,P1.y,P1.z,P1.w},
                     {P2.x,P2.y,P2.z,P2.w},{P3.x,P3.y,P3.z,P3.w}};
    float Earr[4] = {Ev.x,Ev.y,Ev.z,Ev.w};
    float Aarr[4] = {As.x,As.y,As.z,As.w};
    unsigned char cl[4] = {cv.x,cv.y,cv.z,cv.w};

    float Nv[4][4];   // [k][lane]
    float aarr[4], sarr[4];
#pragma unroll
    for (int l = 0; l < 4; l++) {
        float T = P[0][l] + P[1][l] + P[2][l] + P[3][l];
#pragma unroll
        for (int k = 0; k < 4; k++) Nv[k][l] = T - P[k][l];
        float a = 0.f, s = 0.5f;
        int c = cl[l];
        if (c != 0) {
            a = Aarr[l] + Earr[l] - Nv[c - 1][l];
            s = 1.f / (1.f + expf(-a));
        }
        aarr[l] = a; sarr[l] = s;
    }
#pragma unroll
    for (int k = 0; k < 4; k++)
        *(float4*)&g_N[k*KSTRIDE + idx] = make_float4(Nv[k][0],Nv[k][1],Nv[k][2],Nv[k][3]);
    *(float4*)&g_a[idx] = make_float4(aarr[0],aarr[1],aarr[2],aarr[3]);
    *(float4*)&g_s[idx] = make_float4(sarr[0],sarr[1],sarr[2],sarr[3]);
#pragma unroll
    for (int k = 0; k < 4; k++) {
        float x0 = Nv[k][0]*sarr[0], x1 = Nv[k][1]*sarr[1];
        float x2 = Nv[k][2]*sarr[2], x3 = Nv[k][3]*sarr[3];
        __nv_bfloat16 h0 = __float2bfloat16(x0), h1 = __float2bfloat16(x1);
        __nv_bfloat16 h2 = __float2bfloat16(x2), h3 = __float2bfloat16(x3);
        __nv_bfloat162 hp0(h0, h1), hp1(h2, h3);
        __nv_bfloat162 lp0(__float2bfloat16(x0 - __bfloat162float(h0)),
                           __float2bfloat16(x1 - __bfloat162float(h1)));
        __nv_bfloat162 lp1(__float2bfloat16(x2 - __bfloat162float(h2)),
                           __float2bfloat16(x3 - __bfloat162float(h3)));
        *(__nv_bfloat162*)&g_Xhi[k*KSTRIDE + idx]     = hp0;
        *(__nv_bfloat162*)&g_Xhi[k*KSTRIDE + idx + 2] = hp1;
        *(__nv_bfloat162*)&g_Xlo[k*KSTRIDE + idx]     = lp0;
        *(__nv_bfloat162*)&g_Xlo[k*KSTRIDE + idx + 2] = lp1;
    }
}

// ======= update (fused, 4-wide): a += E + Dsel; s; optionally next X =======
__global__ void update_k(int write_x) {
    int v = blockIdx.x * blockDim.x + threadIdx.x;
    if (v >= KSTRIDE/4) return;
    int idx = v * 4;
    uchar4 cv = *(const uchar4*)&g_cls[idx];
    unsigned int cbits;
    memcpy(&cbits, &cv, 4);
    if (cbits == 0u) return;          // all 4 cells empty: nothing changes
    float4 av = *(const float4*)&g_a[idx];
    float4 Ev = *(const float4*)&g_E[idx];
    float4 Dv = *(const float4*)&g_Dsel[idx];
    float aold[4] = {av.x,av.y,av.z,av.w};
    float Earr[4] = {Ev.x,Ev.y,Ev.z,Ev.w};
    float Darr[4] = {Dv.x,Dv.y,Dv.z,Dv.w};
    unsigned char cl[4] = {cv.x,cv.y,cv.z,cv.w};
    float anew[4], sarr[4];
#pragma unroll
    for (int l = 0; l < 4; l++) {
        if (cl[l] != 0) {
            float a = aold[l] + Earr[l] + Darr[l];
            anew[l] = a;
            sarr[l] = 1.f / (1.f + expf(-a));
        } else {
            anew[l] = aold[l];        // unchanged (0)
            sarr[l] = 0.5f;           // empty cells: s fixed at 0.5
        }
    }
    if (write_x) {
        *(float4*)&g_a[idx] = make_float4(anew[0],anew[1],anew[2],anew[3]);
#pragma unroll
        for (int k = 0; k < 4; k++) {
            float4 Nvv = *(const float4*)&g_N[k*KSTRIDE + idx];
            float Nl[4] = {Nvv.x,Nvv.y,Nvv.z,Nvv.w};
            float x0 = Nl[0]*sarr[0], x1 = Nl[1]*sarr[1];
            float x2 = Nl[2]*sarr[2], x3 = Nl[3]*sarr[3];
            __nv_bfloat16 h0 = __float2bfloat16(x0), h1 = __float2bfloat16(x1);
            __nv_bfloat16 h2 = __float2bfloat16(x2), h3 = __float2bfloat16(x3);
            __nv_bfloat162 hp0(h0, h1), hp1(h2, h3);
            __nv_bfloat162 lp0(__float2bfloat16(x0 - __bfloat162float(h0)),
                               __float2bfloat16(x1 - __bfloat162float(h1)));
            __nv_bfloat162 lp1(__float2bfloat16(x2 - __bfloat162float(h2)),
                               __float2bfloat16(x3 - __bfloat162float(h3)));
            *(__nv_bfloat162*)&g_Xhi[k*KSTRIDE + idx]     = hp0;
            *(__nv_bfloat162*)&g_Xhi[k*KSTRIDE + idx + 2] = hp1;
            *(__nv_bfloat162*)&g_Xlo[k*KSTRIDE + idx]     = lp0;
            *(__nv_bfloat162*)&g_Xlo[k*KSTRIDE + idx + 2] = lp1;
        }
    } else {
        *(float4*)&g_s[idx] = make_float4(sarr[0],sarr[1],sarr[2],sarr[3]);
    }
}

// ======= MLP head =======
__global__ __launch_bounds__(256)
void mlp1_k(const float* __restrict__ W1) {
    __shared__ float sS[64][65];
    __shared__ float sW[100][65];
    int tid = threadIdx.x;
    int rowBase = blockIdx.x * 64;
    float acc[25];
#pragma unroll
    for (int i = 0; i < 25; i++) acc[i] = 0.f;
    int r = tid >> 2, cs = (tid & 3) * 25;
    for (int k0 = 0; k0 < 1024; k0 += 64) {
#pragma unroll
        for (int i = 0; i < 16; i++) {
            int e = tid + i * 256; int rr = e >> 6, c = e & 63;
            sS[rr][c] = g_s[(size_t)(rowBase + rr) * 1024 + k0 + c];
        }
#pragma unroll
        for (int i = 0; i < 25; i++) {
            int e = tid + i * 256; int j = e >> 6, c = e & 63;
            sW[j][c] = W1[(size_t)j * 1024 + k0 + c];
        }
        __syncthreads();
#pragma unroll 8
        for (int k = 0; k < 64; k++) {
            float sv = sS[r][k];
#pragma unroll
            for (int j = 0; j < 25; j++) acc[j] += sv * sW[cs + j][k];
        }
        __syncthreads();
    }
#pragma unroll
    for (int j = 0; j < 25; j++) {
        float v = acc[j];
        g_x1[(size_t)(rowBase + r) * 100 + cs + j] = (v > 0.f) ? v : 0.2f * v;
    }
}

__global__ void mlp2_k(const float* __restrict__ W2) {
    int gw = (blockIdx.x * blockDim.x + threadIdx.x) >> 5;
    int lane = threadIdx.x & 31;
    if (gw >= BATCH * 100) return;
    int b = gw / 100, j = gw % 100;
    const float* xrow = g_x1 + (size_t)b * 100;
    const float* wrow = W2 + (size_t)j * 100;
    float acc = 0.f;
    for (int t = lane; t < 100; t += 32) acc += xrow[t] * wrow[t];
#pragma unroll
    for (int o = 16; o; o >>= 1) acc += __shfl_xor_sync(0xffffffffu, acc, o);
    if (lane == 0) g_x2[b * 100 + j] = (acc > 0.f) ? acc : 0.2f * acc;
}

__global__ void mlp3_k(const float* __restrict__ W3, float* __restrict__ out) {
    int gw = (blockIdx.x * blockDim.x + threadIdx.x) >> 5;
    int lane = threadIdx.x & 31;
    if (gw >= BATCH) return;
    const float* xrow = g_x2 + (size_t)gw * 100;
    float acc = 0.f;
    for (int t = lane; t < 100; t += 32) acc += xrow[t] * W3[t];
#pragma unroll
    for (int o = 16; o; o >>= 1) acc += __shfl_xor_sync(0xffffffffu, acc, o);
    if (lane == 0) out[gw] = acc;
}

// ======= launch =======
extern "C" void kernel_launch(void* const* d_in, const int* in_sizes, int n_in,
                              void* d_out, int out_size) {
    (void)in_sizes; (void)n_in; (void)out_size;
    const int*   dots    = (const int*)d_in[0];
    const float* w_each  = (const float*)d_in[1];
    const float* w_not   = (const float*)d_in[2];
    const float* w_not2  = (const float*)d_in[3];
    const float* w_empty = (const float*)d_in[4];
    const float* W1      = (const float*)d_in[5];
    const float* W2      = (const float*)d_in[6];
    const float* W3      = (const float*)d_in[7];
    float* out = (float*)d_out;

    const int SMEM = 3 * STAGEB;   // 98304
    cudaFuncSetAttribute(mma_gemm_k, cudaFuncAttributeMaxDynamicSharedMemorySize, SMEM);

    build_B_k<<<(CELLS*CELLS + 255)/256, 256>>>(w_each, w_not, w_not2, w_empty);
    build_masks_k<<<(KSTRIDE + 255)/256, 256>>>(dots);

    // phase A: Asel(masked) + P + E in one launch
    mma_gemm_k<<<dim3(24, 128), 256, SMEM>>>(1);

    init_k<<<(KSTRIDE/4 + 255)/256, 256>>>();

    for (int d = 0; d < 4; d++) {
        mma_gemm_k<<<dim3(8, 128), 256, SMEM>>>(3);   // D (interleaved 3-pass, masked)
        update_k<<<(KSTRIDE/4 + 255)/256, 256>>>(d < 3 ? 1 : 0);
    }

    mlp1_k<<<BATCH/64, 256>>>(W1);
    {
        long nw = (long)BATCH * 100 * 32;
        mlp2_k<<<(unsigned)((nw + 255)/256), 256>>>(W2);
        long nw3 = (long)BATCH * 32;
        mlp3_k<<<(unsigned)((nw3 + 255)/256), 256>>>(W3, out);
    }
}